// round 16
// baseline (speedup 1.0000x reference)
#include <cuda_runtime.h>
#include <cuda_bf16.h>
#include <math.h>
#include <stdint.h>

// ---------------- problem constants ----------------
#define DIMF     128
#define DTIME    100
#define LDQ      228
#define LDKV     356
#define LDOUT    256
#define MAXD     25024
#define MAXE     250048
#define LN_EPS   1e-5f
#define KX       384      // padded kv-input dim (356 feats + bias col at 356, zeros after)
#define NEG_INF  (-3.402823466e38f)

// ---------------- device scratch (static, allocation-free) ----------------
__device__ float g_Q   [(size_t)MAXD * DIMF];
__device__ float g_h   [(size_t)MAXD * DIMF];
__device__ float g_rst [(size_t)MAXD * DIMF];
__device__ float g_qb2 [DIMF];
__device__ int   g_nstart[MAXD + 2];
__device__ float g_xbar[(size_t)MAXD * 8 * KX];   // per-dst normalized att-weighted input

// ---------------- small precompute kernels ----------------
__global__ void qb2_kernel(const float* __restrict__ wq_w,
                           const float* __restrict__ wq_b,
                           const float* __restrict__ time_b) {
    int o = threadIdx.x;
    if (o >= DIMF) return;
    float s = wq_b[o];
    #pragma unroll 4
    for (int t = 0; t < DTIME; t++)
        s += wq_w[(size_t)o * LDQ + DIMF + t] * cosf(time_b[t]);
    g_qb2[o] = s;
}

__global__ void nstart_kernel(const int* __restrict__ edge_dst, int E, int D) {
    int d = blockIdx.x * blockDim.x + threadIdx.x;
    if (d > D) return;
    int lo = 0, hi = E;
    while (lo < hi) {
        int mid = (lo + hi) >> 1;
        if (edge_dst[mid] < d) lo = mid + 1; else hi = mid;
    }
    g_nstart[d] = lo;
}

// ---------------- Q projection (scalar SGEMM, small) ----------------
__global__ __launch_bounds__(256)
void gemm_q(const float* __restrict__ W,
            const float* __restrict__ sf, const int* __restrict__ sidx, int M) {
    __shared__ float As[16][132];
    __shared__ float Bs[16][132];

    const int tid = threadIdx.x;
    const int i0  = blockIdx.x * 128;
    const int lr  = tid >> 1;
    const int lk  = (tid & 1) * 8;
    const int tx  = tid & 15;
    const int ty  = tid >> 4;

    float acc[8][8];
    #pragma unroll
    for (int i = 0; i < 8; i++)
        #pragma unroll
        for (int j = 0; j < 8; j++) acc[i][j] = 0.f;

    for (int k0 = 0; k0 < DIMF; k0 += 16) {
        {
            int row = i0 + lr;
            #pragma unroll
            for (int j = 0; j < 8; j++) {
                int k = k0 + lk + j;
                As[lk + j][lr] = (row < M) ? sf[(size_t)sidx[row] * DIMF + k] : 0.f;
            }
        }
        {
            #pragma unroll
            for (int j = 0; j < 8; j++) {
                int k = k0 + lk + j;
                Bs[lk + j][lr] = W[(size_t)lr * LDQ + k];
            }
        }
        __syncthreads();
        #pragma unroll
        for (int kk = 0; kk < 16; kk++) {
            float4 a0 = *(const float4*)&As[kk][ty * 8];
            float4 a1 = *(const float4*)&As[kk][ty * 8 + 4];
            float4 b0 = *(const float4*)&Bs[kk][tx * 8];
            float4 b1 = *(const float4*)&Bs[kk][tx * 8 + 4];
            float ar[8] = {a0.x, a0.y, a0.z, a0.w, a1.x, a1.y, a1.z, a1.w};
            float br[8] = {b0.x, b0.y, b0.z, b0.w, b1.x, b1.y, b1.z, b1.w};
            #pragma unroll
            for (int i = 0; i < 8; i++)
                #pragma unroll
                for (int j = 0; j < 8; j++)
                    acc[i][j] += ar[i] * br[j];
        }
        __syncthreads();
    }
    #pragma unroll
    for (int i = 0; i < 8; i++) {
        int row = i0 + ty * 8 + i;
        if (row >= M) continue;
        #pragma unroll
        for (int j = 0; j < 8; j++) {
            int col = tx * 8 + j;
            g_Q[(size_t)row * DIMF + col] = acc[i][j] + g_qb2[col];
        }
    }
}

// ---------------- fused edge kernel: in-smem tQ + online softmax ----------------
// CTA: 256 threads, 4 destinations.
// Phase 1: compute tQ[dd][h][k] = sum_j Q[d,16h+j]*wk_ext[16h+j,k] into smem
//          (head-pairs staged; warp = (head-of-pair, dst))
// Phase 2: warp = (dst, 4-head group) online-softmax edge loop (tQ from smem)
// smem layout (floats): Qs[4][128] | wks[2][16][KX] | tQs[4][8][KX]
#define SM_QS    0
#define SM_WKS   (4 * 128)
#define SM_TQS   (SM_WKS + 2 * 16 * KX)
#define EDGE_SMEM ((SM_TQS + 4 * 8 * KX) * 4)   // 100,352 bytes

__device__ __forceinline__ void load_x(float* xv, int lane, int e,
                                       const float* __restrict__ sf,
                                       const int* __restrict__ sidx,
                                       const float* __restrict__ ef,
                                       const float* __restrict__ edt,
                                       const float* __restrict__ tw,
                                       const float* __restrict__ tb,
                                       int D) {
    int row = sidx[D + e];
    float dt = edt[e];
    #pragma unroll
    for (int t = 0; t < 4; t++)
        xv[t] = sf[(size_t)row * DIMF + lane + 32 * t];
    #pragma unroll
    for (int t = 4; t < 8; t++)
        xv[t] = ef[(size_t)e * DIMF + lane + 32 * t - DIMF];
    #pragma unroll
    for (int t = 8; t < 11; t++) {
        int ti = lane + 32 * t - 2 * DIMF;
        xv[t] = __cosf(fmaf(dt, tw[ti], tb[ti]));
    }
    {
        int k = lane + 32 * 11;
        if (k < LDKV)       xv[11] = __cosf(fmaf(dt, tw[k - 2 * DIMF], tb[k - 2 * DIMF]));
        else if (k == LDKV) xv[11] = 1.f;     // homogeneous coord (bias / att-mass)
        else                xv[11] = 0.f;
    }
}

__global__ __launch_bounds__(256)
void edge_kernel(const float* __restrict__ sf, const int* __restrict__ sidx,
                 const float* __restrict__ ef, const float* __restrict__ edt,
                 const float* __restrict__ tw, const float* __restrict__ tb,
                 const float* __restrict__ wk, const float* __restrict__ wk_b,
                 int D, int E) {
    extern __shared__ float sm[];
    float* Qs  = sm + SM_QS;    // [4][128]
    float* wks = sm + SM_WKS;   // [2][16][KX]
    float* tQs = sm + SM_TQS;   // [4][8][KX]

    const int tid  = threadIdx.x;
    const int wid  = tid >> 5;
    const int lane = tid & 31;
    const int d0   = blockIdx.x * 4;

    // ---- stage Q tile (4 dsts x 128) ----
    #pragma unroll
    for (int i = tid; i < 4 * 128; i += 256) {
        int dd = i >> 7, j = i & 127;
        int d = d0 + dd;
        Qs[i] = (d < D) ? g_Q[(size_t)d * DIMF + j] : 0.f;
    }
    __syncthreads();

    // ---- phase 1: 4 head-pairs ----
    const int p1_hh = wid >> 2;      // head within pair
    const int p1_dd = wid & 3;       // destination
    for (int pr = 0; pr < 4; pr++) {
        // stage wk_ext rows for heads 2*pr, 2*pr+1
        for (int i = tid; i < 2 * 16 * KX; i += 256) {
            int hh = i / (16 * KX);
            int rem = i - hh * (16 * KX);
            int r = rem / KX;
            int k = rem - r * KX;
            int rc = (pr * 2 + hh) * 16 + r;
            float v;
            if (k < LDKV)       v = wk[(size_t)rc * LDKV + k];
            else if (k == LDKV) v = wk_b[rc];
            else                v = 0.f;
            wks[i] = v;
        }
        __syncthreads();

        // warp computes tQ slice for (head p1_hh of pair, dst p1_dd)
        {
            float a[12];
            #pragma unroll
            for (int i = 0; i < 12; i++) a[i] = 0.f;
            const float* wb = wks + p1_hh * (16 * KX);
            const float* qb = Qs + p1_dd * 128 + (pr * 2 + p1_hh) * 16;
            #pragma unroll
            for (int j = 0; j < 16; j++) {
                float q = qb[j];
                float4 w0 = *(const float4*)&wb[j * KX + lane * 4];
                float4 w1 = *(const float4*)&wb[j * KX + 128 + lane * 4];
                float4 w2 = *(const float4*)&wb[j * KX + 256 + lane * 4];
                a[0]  = fmaf(q, w0.x, a[0]);
                a[1]  = fmaf(q, w0.y, a[1]);
                a[2]  = fmaf(q, w0.z, a[2]);
                a[3]  = fmaf(q, w0.w, a[3]);
                a[4]  = fmaf(q, w1.x, a[4]);
                a[5]  = fmaf(q, w1.y, a[5]);
                a[6]  = fmaf(q, w1.z, a[6]);
                a[7]  = fmaf(q, w1.w, a[7]);
                a[8]  = fmaf(q, w2.x, a[8]);
                a[9]  = fmaf(q, w2.y, a[9]);
                a[10] = fmaf(q, w2.z, a[10]);
                a[11] = fmaf(q, w2.w, a[11]);
            }
            float* out = tQs + (p1_dd * 8 + pr * 2 + p1_hh) * KX;
            *(float4*)&out[lane * 4]       = make_float4(a[0], a[1], a[2], a[3]);
            *(float4*)&out[128 + lane * 4] = make_float4(a[4], a[5], a[6], a[7]);
            *(float4*)&out[256 + lane * 4] = make_float4(a[8], a[9], a[10], a[11]);
        }
        __syncthreads();
    }

    // ---- phase 2: edge loop; warp = (dst, head-group) ----
    const int dd = wid >> 1;
    const int hg = wid & 1;
    const int d  = d0 + dd;
    if (d >= D) return;

    int s0 = g_nstart[d];
    int e0 = g_nstart[d + 1];

    float tQr[4][12];
    #pragma unroll
    for (int hh = 0; hh < 4; hh++)
        #pragma unroll
        for (int t = 0; t < 12; t++)
            tQr[hh][t] = tQs[(dd * 8 + hg * 4 + hh) * KX + lane + 32 * t];

    float m[4], den[4], xacc[4][12];
    #pragma unroll
    for (int hh = 0; hh < 4; hh++) {
        m[hh] = NEG_INF; den[hh] = 0.f;
        #pragma unroll
        for (int t = 0; t < 12; t++) xacc[hh][t] = 0.f;
    }

    for (int e = s0; e < e0; e++) {
        float xv[12];
        load_x(xv, lane, e, sf, sidx, ef, edt, tw, tb, D);

        float sh[4];
        #pragma unroll
        for (int hh = 0; hh < 4; hh++) sh[hh] = 0.f;
        #pragma unroll
        for (int t = 0; t < 12; t++)
            #pragma unroll
            for (int hh = 0; hh < 4; hh++)
                sh[hh] = fmaf(tQr[hh][t], xv[t], sh[hh]);
        #pragma unroll
        for (int hh = 0; hh < 4; hh++) {
            #pragma unroll
            for (int o = 16; o > 0; o >>= 1)
                sh[hh] += __shfl_xor_sync(0xffffffffu, sh[hh], o);
            sh[hh] = (sh[hh] > 0.f) ? sh[hh] : 0.2f * sh[hh];   // leaky_relu 0.2
        }

        // online softmax-weighted accumulation (warp-uniform branches)
        #pragma unroll
        for (int hh = 0; hh < 4; hh++) {
            if (sh[hh] > m[hh]) {
                float c = __expf(m[hh] - sh[hh]);   // 0 on first edge
                den[hh] = fmaf(den[hh], c, 1.f);
                #pragma unroll
                for (int t = 0; t < 12; t++)
                    xacc[hh][t] = fmaf(xacc[hh][t], c, xv[t]);
                m[hh] = sh[hh];
            } else {
                float wt = __expf(sh[hh] - m[hh]);
                den[hh] += wt;
                #pragma unroll
                for (int t = 0; t < 12; t++)
                    xacc[hh][t] = fmaf(wt, xv[t], xacc[hh][t]);
            }
        }
    }

    #pragma unroll
    for (int hh = 0; hh < 4; hh++) {
        float inv = (den[hh] > 0.f) ? 1.f / den[hh] : 0.f;
        #pragma unroll
        for (int t = 0; t < 12; t++)
            g_xbar[((size_t)d * 8 + hg * 4 + hh) * KX + lane + 32 * t]
                = xacc[hh][t] * inv;
    }
}

// ---------------- hproj: warp per (head, dst-pair), float4 streaming ----------------
// h[d, 16h+j] = sum_k wv_ext[16h+j, k] * xbar[d][h][k]; bias via homogeneous coord
__global__ __launch_bounds__(256)
void hproj_kernel(const float* __restrict__ wv, const float* __restrict__ wv_b, int D) {
    int w    = (blockIdx.x * 256 + threadIdx.x) >> 5;
    int lane = threadIdx.x & 31;
    int npair = (D + 1) >> 1;
    if (w >= 8 * npair) return;
    int h = w & 7;
    int p = w >> 3;
    int dl = lane >> 4;          // 0..1
    int j  = lane & 15;
    int d  = p * 2 + dl;
    bool valid = (d < D);
    int c = h * 16 + j;

    const float* xrow = g_xbar + ((size_t)(valid ? d : 0) * 8 + h) * KX;
    const float* wrow = wv + (size_t)c * LDKV;

    float acc = 0.f;
    #pragma unroll 4
    for (int k4 = 0; k4 < 89; k4++) {           // k = 0..355
        float4 x = *(const float4*)&xrow[k4 * 4];
        float4 wv4 = *(const float4*)&wrow[k4 * 4];
        acc = fmaf(x.x, wv4.x, acc);
        acc = fmaf(x.y, wv4.y, acc);
        acc = fmaf(x.z, wv4.z, acc);
        acc = fmaf(x.w, wv4.w, acc);
    }
    acc = fmaf(xrow[LDKV], __ldg(&wv_b[c]), acc);   // bias * (att mass)

    if (valid) g_h[(size_t)d * DIMF + c] = acc;
}

// ---------------- output projection + ReLU (scalar SGEMM) ----------------
__global__ __launch_bounds__(256)
void gemm_out(const float* __restrict__ W, const float* __restrict__ bias,
              const float* __restrict__ sf, const int* __restrict__ sidx, int M) {
    __shared__ float As[16][132];
    __shared__ float Bs[16][132];

    const int tid = threadIdx.x;
    const int i0  = blockIdx.x * 128;
    const int lr  = tid >> 1;
    const int lk  = (tid & 1) * 8;
    const int tx  = tid & 15;
    const int ty  = tid >> 4;

    float acc[8][8];
    #pragma unroll
    for (int i = 0; i < 8; i++)
        #pragma unroll
        for (int j = 0; j < 8; j++) acc[i][j] = 0.f;

    for (int k0 = 0; k0 < LDOUT; k0 += 16) {
        {
            int row = i0 + lr;
            #pragma unroll
            for (int j = 0; j < 8; j++) {
                int k = k0 + lk + j;
                float v = 0.f;
                if (row < M) {
                    if (k < DIMF) v = g_h[(size_t)row * DIMF + k];
                    else          v = sf[(size_t)sidx[row] * DIMF + (k - DIMF)];
                }
                As[lk + j][lr] = v;
            }
        }
        {
            #pragma unroll
            for (int j = 0; j < 8; j++) {
                int k = k0 + lk + j;
                Bs[lk + j][lr] = W[(size_t)lr * LDOUT + k];
            }
        }
        __syncthreads();
        #pragma unroll
        for (int kk = 0; kk < 16; kk++) {
            float4 a0 = *(const float4*)&As[kk][ty * 8];
            float4 a1 = *(const float4*)&As[kk][ty * 8 + 4];
            float4 b0 = *(const float4*)&Bs[kk][tx * 8];
            float4 b1 = *(const float4*)&Bs[kk][tx * 8 + 4];
            float ar[8] = {a0.x, a0.y, a0.z, a0.w, a1.x, a1.y, a1.z, a1.w};
            float br[8] = {b0.x, b0.y, b0.z, b0.w, b1.x, b1.y, b1.z, b1.w};
            #pragma unroll
            for (int i = 0; i < 8; i++)
                #pragma unroll
                for (int j = 0; j < 8; j++)
                    acc[i][j] += ar[i] * br[j];
        }
        __syncthreads();
    }
    #pragma unroll
    for (int i = 0; i < 8; i++) {
        int row = i0 + ty * 8 + i;
        if (row >= M) continue;
        #pragma unroll
        for (int j = 0; j < 8; j++) {
            int col = tx * 8 + j;
            g_rst[(size_t)row * DIMF + col] = fmaxf(acc[i][j] + bias[col], 0.f);
        }
    }
}

// ---------------- layernorm (warp per row) ----------------
__global__ __launch_bounds__(256)
void ln_kernel(const float* __restrict__ ln_g, const float* __restrict__ ln_b,
               float* __restrict__ out, int D) {
    int row = (blockIdx.x * blockDim.x + threadIdx.x) >> 5;
    int lane = threadIdx.x & 31;
    if (row >= D) return;

    float4 v = *(const float4*)&g_rst[(size_t)row * DIMF + lane * 4];
    float s  = v.x + v.y + v.z + v.w;
    float s2 = v.x * v.x + v.y * v.y + v.z * v.z + v.w * v.w;
    #pragma unroll
    for (int off = 16; off > 0; off >>= 1) {
        s  += __shfl_xor_sync(0xffffffffu, s,  off);
        s2 += __shfl_xor_sync(0xffffffffu, s2, off);
    }
    float mean = s * (1.f / DIMF);
    float var  = s2 * (1.f / DIMF) - mean * mean;
    float rstd = rsqrtf(var + LN_EPS);

    float4 g = *(const float4*)&ln_g[lane * 4];
    float4 b = *(const float4*)&ln_b[lane * 4];
    float4 o;
    o.x = (v.x - mean) * rstd * g.x + b.x;
    o.y = (v.y - mean) * rstd * g.y + b.y;
    o.z = (v.z - mean) * rstd * g.z + b.z;
    o.w = (v.w - mean) * rstd * g.w + b.w;
    *(float4*)&out[(size_t)row * DIMF + lane * 4] = o;
}

// ---------------- launcher ----------------
extern "C" void kernel_launch(void* const* d_in, const int* in_sizes, int n_in,
                              void* d_out, int out_size) {
    const float* src_feat = (const float*)d_in[0];
    const float* edge_f   = (const float*)d_in[1];
    const float* edge_dt  = (const float*)d_in[2];
    const float* time_w   = (const float*)d_in[3];
    const float* time_b   = (const float*)d_in[4];
    const float* wq_w     = (const float*)d_in[5];
    const float* wq_b     = (const float*)d_in[6];
    const float* wk_w     = (const float*)d_in[7];
    const float* wk_b     = (const float*)d_in[8];
    const float* wv_w     = (const float*)d_in[9];
    const float* wv_b     = (const float*)d_in[10];
    const float* wout_w   = (const float*)d_in[11];
    const float* wout_b   = (const float*)d_in[12];
    const float* ln_g     = (const float*)d_in[13];
    const float* ln_b     = (const float*)d_in[14];
    const int*   src_idx  = (const int*)d_in[15];   // JAX x64-disabled: int32
    const int*   edge_dst = (const int*)d_in[16];   // JAX x64-disabled: int32

    const int E = in_sizes[1] / DIMF;
    const int D = in_sizes[0] / DIMF - E;

    static bool attr_set = []() {
        cudaFuncSetAttribute(edge_kernel,
                             cudaFuncAttributeMaxDynamicSharedMemorySize, EDGE_SMEM);
        return true;
    }();
    (void)attr_set;

    qb2_kernel<<<1, 128>>>(wq_w, wq_b, time_b);
    nstart_kernel<<<(D + 1 + 255) / 256, 256>>>(edge_dst, E, D);

    // Qd = gathered node feats @ wq[:, :128]^T + qb2
    gemm_q<<<(D + 127) / 128, 256>>>(wq_w, src_feat, src_idx, D);

    // fused: in-smem tQ + online-softmax attention -> normalized xbar
    edge_kernel<<<(D + 3) / 4, 256, EDGE_SMEM>>>(src_feat, src_idx, edge_f, edge_dt,
                                                 time_w, time_b, wk_w, wk_b, D, E);

    // h[d] = Wv_ext @ xbar[d]
    {
        int warps = 8 * ((D + 1) / 2);
        hproj_kernel<<<(warps * 32 + 255) / 256, 256>>>(wv_w, wv_b, D);
    }

    // output projection + ReLU
    gemm_out<<<(D + 127) / 128, 256>>>(wout_w, wout_b, src_feat, src_idx, D);

    ln_kernel<<<(D + 7) / 8, 256>>>(ln_g, ln_b, (float*)d_out, D);
}

// round 17
// speedup vs baseline: 2.7947x; 2.7947x over previous
#include <cuda_runtime.h>
#include <cuda_bf16.h>
#include <math.h>
#include <stdint.h>

// ---------------- problem constants ----------------
#define DIMF     128
#define DTIME    100
#define LDQ      228
#define LDKV     356
#define LDOUT    256
#define MAXD     25024
#define MAXE     250048
#define LN_EPS   1e-5f
#define KX       384      // padded kv-input dim (356 feats + bias col at 356, zeros after)
#define NEG_INF  (-3.402823466e38f)

// ---------------- device scratch (static, allocation-free) ----------------
__device__ float g_Q   [(size_t)MAXD * DIMF];
__device__ float g_h   [(size_t)MAXD * DIMF];
__device__ float g_qb2 [DIMF];
__device__ int   g_nstart[MAXD + 2];
__device__ float g_tQ  [(size_t)MAXD * 8 * KX];   // per-dst folded query: tQ[d][h][k]
__device__ float g_xbar[(size_t)MAXD * 8 * KX];   // per-dst normalized att-weighted input

// ---------------- small precompute kernels ----------------
__global__ void qb2_kernel(const float* __restrict__ wq_w,
                           const float* __restrict__ wq_b,
                           const float* __restrict__ time_b) {
    int o = threadIdx.x;
    if (o >= DIMF) return;
    float s = wq_b[o];
    #pragma unroll 4
    for (int t = 0; t < DTIME; t++)
        s += wq_w[(size_t)o * LDQ + DIMF + t] * cosf(time_b[t]);
    g_qb2[o] = s;
}

__global__ void nstart_kernel(const int* __restrict__ edge_dst, int E, int D) {
    int d = blockIdx.x * blockDim.x + threadIdx.x;
    if (d > D) return;
    int lo = 0, hi = E;
    while (lo < hi) {
        int mid = (lo + hi) >> 1;
        if (edge_dst[mid] < d) lo = mid + 1; else hi = mid;
    }
    g_nstart[d] = lo;
}

// ---------------- Q projection (scalar SGEMM, small) ----------------
__global__ __launch_bounds__(256)
void gemm_q(const float* __restrict__ W,
            const float* __restrict__ sf, const int* __restrict__ sidx, int M) {
    __shared__ float As[16][132];
    __shared__ float Bs[16][132];

    const int tid = threadIdx.x;
    const int i0  = blockIdx.x * 128;
    const int lr  = tid >> 1;
    const int lk  = (tid & 1) * 8;
    const int tx  = tid & 15;
    const int ty  = tid >> 4;

    float acc[8][8];
    #pragma unroll
    for (int i = 0; i < 8; i++)
        #pragma unroll
        for (int j = 0; j < 8; j++) acc[i][j] = 0.f;

    for (int k0 = 0; k0 < DIMF; k0 += 16) {
        {
            int row = i0 + lr;
            #pragma unroll
            for (int j = 0; j < 8; j++) {
                int k = k0 + lk + j;
                As[lk + j][lr] = (row < M) ? sf[(size_t)sidx[row] * DIMF + k] : 0.f;
            }
        }
        {
            #pragma unroll
            for (int j = 0; j < 8; j++) {
                int k = k0 + lk + j;
                Bs[lk + j][lr] = W[(size_t)lr * LDQ + k];
            }
        }
        __syncthreads();
        #pragma unroll
        for (int kk = 0; kk < 16; kk++) {
            float4 a0 = *(const float4*)&As[kk][ty * 8];
            float4 a1 = *(const float4*)&As[kk][ty * 8 + 4];
            float4 b0 = *(const float4*)&Bs[kk][tx * 8];
            float4 b1 = *(const float4*)&Bs[kk][tx * 8 + 4];
            float ar[8] = {a0.x, a0.y, a0.z, a0.w, a1.x, a1.y, a1.z, a1.w};
            float br[8] = {b0.x, b0.y, b0.z, b0.w, b1.x, b1.y, b1.z, b1.w};
            #pragma unroll
            for (int i = 0; i < 8; i++)
                #pragma unroll
                for (int j = 0; j < 8; j++)
                    acc[i][j] += ar[i] * br[j];
        }
        __syncthreads();
    }
    #pragma unroll
    for (int i = 0; i < 8; i++) {
        int row = i0 + ty * 8 + i;
        if (row >= M) continue;
        #pragma unroll
        for (int j = 0; j < 8; j++) {
            int col = tx * 8 + j;
            g_Q[(size_t)row * DIMF + col] = acc[i][j] + g_qb2[col];
        }
    }
}

// ---------------- tQ: CTA = (head, 32-dst tile); wk_h staged in smem ----------------
// tQ[d][h][k] = sum_j Q[d, 16h+j] * wk_ext[16h+j, k];  wk_ext[:,356]=wk_b, rest 0
__global__ __launch_bounds__(256, 3)
void tq_kernel(const float* __restrict__ wk, const float* __restrict__ wk_b, int D) {
    __shared__ float wks[16][KX];     // head's 16 extended rows
    __shared__ float Qs[32][16];      // 32 dsts x 16 head-cols

    const int h  = blockIdx.y;
    const int d0 = blockIdx.x * 32;
    const int tid = threadIdx.x;

    for (int i = tid; i < 16 * KX; i += 256) {
        int r = i / KX, k = i - r * KX;
        int rc = h * 16 + r;
        float v;
        if (k < LDKV)       v = wk[(size_t)rc * LDKV + k];
        else if (k == LDKV) v = wk_b[rc];
        else                v = 0.f;
        wks[r][k] = v;
    }
    for (int i = tid; i < 32 * 16; i += 256) {
        int dl = i >> 4, j = i & 15;
        int d = d0 + dl;
        Qs[dl][j] = (d < D) ? g_Q[(size_t)d * DIMF + h * 16 + j] : 0.f;
    }
    __syncthreads();

    const int wid  = tid >> 5;     // 8 warps -> 4 dsts each
    const int lane = tid & 31;

    float acc[4][12];
    #pragma unroll
    for (int dd = 0; dd < 4; dd++)
        #pragma unroll
        for (int i = 0; i < 12; i++) acc[dd][i] = 0.f;

    #pragma unroll
    for (int j = 0; j < 16; j++) {
        float4 w0 = *(const float4*)&wks[j][lane * 4];
        float4 w1 = *(const float4*)&wks[j][128 + lane * 4];
        float4 w2 = *(const float4*)&wks[j][256 + lane * 4];
        #pragma unroll
        for (int dd = 0; dd < 4; dd++) {
            float q = Qs[wid * 4 + dd][j];
            acc[dd][0]  = fmaf(q, w0.x, acc[dd][0]);
            acc[dd][1]  = fmaf(q, w0.y, acc[dd][1]);
            acc[dd][2]  = fmaf(q, w0.z, acc[dd][2]);
            acc[dd][3]  = fmaf(q, w0.w, acc[dd][3]);
            acc[dd][4]  = fmaf(q, w1.x, acc[dd][4]);
            acc[dd][5]  = fmaf(q, w1.y, acc[dd][5]);
            acc[dd][6]  = fmaf(q, w1.z, acc[dd][6]);
            acc[dd][7]  = fmaf(q, w1.w, acc[dd][7]);
            acc[dd][8]  = fmaf(q, w2.x, acc[dd][8]);
            acc[dd][9]  = fmaf(q, w2.y, acc[dd][9]);
            acc[dd][10] = fmaf(q, w2.z, acc[dd][10]);
            acc[dd][11] = fmaf(q, w2.w, acc[dd][11]);
        }
    }

    #pragma unroll
    for (int dd = 0; dd < 4; dd++) {
        int d = d0 + wid * 4 + dd;
        if (d >= D) continue;
        float* out = &g_tQ[((size_t)d * 8 + h) * KX];
        *(float4*)&out[lane * 4]       = make_float4(acc[dd][0], acc[dd][1], acc[dd][2], acc[dd][3]);
        *(float4*)&out[128 + lane * 4] = make_float4(acc[dd][4], acc[dd][5], acc[dd][6], acc[dd][7]);
        *(float4*)&out[256 + lane * 4] = make_float4(acc[dd][8], acc[dd][9], acc[dd][10], acc[dd][11]);
    }
}

// ---------------- edge kernel: warp per (dst, 4-head group), online softmax ----------------
__device__ __forceinline__ void load_x(float* xv, int lane, int e,
                                       const float* __restrict__ sf,
                                       const int* __restrict__ sidx,
                                       const float* __restrict__ ef,
                                       const float* __restrict__ edt,
                                       const float* __restrict__ tw,
                                       const float* __restrict__ tb,
                                       int D) {
    int row = sidx[D + e];
    float dt = edt[e];
    #pragma unroll
    for (int t = 0; t < 4; t++)
        xv[t] = sf[(size_t)row * DIMF + lane + 32 * t];
    #pragma unroll
    for (int t = 4; t < 8; t++)
        xv[t] = ef[(size_t)e * DIMF + lane + 32 * t - DIMF];
    #pragma unroll
    for (int t = 8; t < 11; t++) {
        int ti = lane + 32 * t - 2 * DIMF;
        xv[t] = __cosf(fmaf(dt, tw[ti], tb[ti]));
    }
    {
        int k = lane + 32 * 11;
        if (k < LDKV)       xv[11] = __cosf(fmaf(dt, tw[k - 2 * DIMF], tb[k - 2 * DIMF]));
        else if (k == LDKV) xv[11] = 1.f;     // homogeneous coord (bias / att-mass)
        else                xv[11] = 0.f;
    }
}

__global__ __launch_bounds__(128)
void edge_kernel(const float* __restrict__ sf, const int* __restrict__ sidx,
                 const float* __restrict__ ef, const float* __restrict__ edt,
                 const float* __restrict__ tw, const float* __restrict__ tb,
                 int D, int E) {
    int w    = (blockIdx.x * 128 + threadIdx.x) >> 5;   // global warp id
    int lane = threadIdx.x & 31;
    int d    = w >> 1;          // destination
    int hg   = w & 1;           // head group (4 heads each)
    if (d >= D) return;

    int s0 = g_nstart[d];
    int e0 = g_nstart[d + 1];

    float tQr[4][12];
    #pragma unroll
    for (int hh = 0; hh < 4; hh++)
        #pragma unroll
        for (int t = 0; t < 12; t++)
            tQr[hh][t] = g_tQ[((size_t)d * 8 + hg * 4 + hh) * KX + lane + 32 * t];

    float m[4], den[4], xacc[4][12];
    #pragma unroll
    for (int hh = 0; hh < 4; hh++) {
        m[hh] = NEG_INF; den[hh] = 0.f;
        #pragma unroll
        for (int t = 0; t < 12; t++) xacc[hh][t] = 0.f;
    }

    for (int e = s0; e < e0; e++) {
        float xv[12];
        load_x(xv, lane, e, sf, sidx, ef, edt, tw, tb, D);

        float sh[4];
        #pragma unroll
        for (int hh = 0; hh < 4; hh++) sh[hh] = 0.f;
        #pragma unroll
        for (int t = 0; t < 12; t++)
            #pragma unroll
            for (int hh = 0; hh < 4; hh++)
                sh[hh] = fmaf(tQr[hh][t], xv[t], sh[hh]);
        #pragma unroll
        for (int hh = 0; hh < 4; hh++) {
            #pragma unroll
            for (int o = 16; o > 0; o >>= 1)
                sh[hh] += __shfl_xor_sync(0xffffffffu, sh[hh], o);
            sh[hh] = (sh[hh] > 0.f) ? sh[hh] : 0.2f * sh[hh];   // leaky_relu 0.2
        }

        // online softmax-weighted accumulation (warp-uniform branches)
        #pragma unroll
        for (int hh = 0; hh < 4; hh++) {
            if (sh[hh] > m[hh]) {
                float c = __expf(m[hh] - sh[hh]);   // 0 on first edge
                den[hh] = fmaf(den[hh], c, 1.f);
                #pragma unroll
                for (int t = 0; t < 12; t++)
                    xacc[hh][t] = fmaf(xacc[hh][t], c, xv[t]);
                m[hh] = sh[hh];
            } else {
                float wt = __expf(sh[hh] - m[hh]);
                den[hh] += wt;
                #pragma unroll
                for (int t = 0; t < 12; t++)
                    xacc[hh][t] = fmaf(wt, xv[t], xacc[hh][t]);
            }
        }
    }

    #pragma unroll
    for (int hh = 0; hh < 4; hh++) {
        float inv = (den[hh] > 0.f) ? 1.f / den[hh] : 0.f;
        #pragma unroll
        for (int t = 0; t < 12; t++)
            g_xbar[((size_t)d * 8 + hg * 4 + hh) * KX + lane + 32 * t]
                = xacc[hh][t] * inv;
    }
}

// ---------------- hproj: warp per (head, dst-pair), float4 streaming ----------------
// h[d, 16h+j] = sum_k wv_ext[16h+j, k] * xbar[d][h][k]; bias via homogeneous coord
__global__ __launch_bounds__(256)
void hproj_kernel(const float* __restrict__ wv, const float* __restrict__ wv_b, int D) {
    int w    = (blockIdx.x * 256 + threadIdx.x) >> 5;
    int lane = threadIdx.x & 31;
    int npair = (D + 1) >> 1;
    if (w >= 8 * npair) return;
    int h = w & 7;
    int p = w >> 3;
    int dl = lane >> 4;          // 0..1
    int j  = lane & 15;
    int d  = p * 2 + dl;
    bool valid = (d < D);
    int c = h * 16 + j;

    const float* xrow = g_xbar + ((size_t)(valid ? d : 0) * 8 + h) * KX;
    const float* wrow = wv + (size_t)c * LDKV;

    float acc = 0.f;
    #pragma unroll 4
    for (int k4 = 0; k4 < 89; k4++) {           // k = 0..355
        float4 x = *(const float4*)&xrow[k4 * 4];
        float4 wv4 = *(const float4*)&wrow[k4 * 4];
        acc = fmaf(x.x, wv4.x, acc);
        acc = fmaf(x.y, wv4.y, acc);
        acc = fmaf(x.z, wv4.z, acc);
        acc = fmaf(x.w, wv4.w, acc);
    }
    acc = fmaf(xrow[LDKV], __ldg(&wv_b[c]), acc);   // bias * (att mass)

    if (valid) g_h[(size_t)d * DIMF + c] = acc;
}

// ---------------- output projection + ReLU + LayerNorm (fused epilogue) ----------------
__global__ __launch_bounds__(256)
void gemm_out(const float* __restrict__ W, const float* __restrict__ bias,
              const float* __restrict__ sf, const int* __restrict__ sidx,
              const float* __restrict__ ln_g, const float* __restrict__ ln_b,
              float* __restrict__ outp, int M) {
    __shared__ float As[16][132];
    __shared__ float Bs[16][132];
    __shared__ float redS [128][17];   // per-row partial sums (16 tx slots, padded)
    __shared__ float redS2[128][17];   // per-row partial sumsq
    __shared__ float rowMean[128];
    __shared__ float rowRstd[128];

    const int tid = threadIdx.x;
    const int i0  = blockIdx.x * 128;
    const int lr  = tid >> 1;
    const int lk  = (tid & 1) * 8;
    const int tx  = tid & 15;
    const int ty  = tid >> 4;

    float acc[8][8];
    #pragma unroll
    for (int i = 0; i < 8; i++)
        #pragma unroll
        for (int j = 0; j < 8; j++) acc[i][j] = 0.f;

    for (int k0 = 0; k0 < LDOUT; k0 += 16) {
        {
            int row = i0 + lr;
            #pragma unroll
            for (int j = 0; j < 8; j++) {
                int k = k0 + lk + j;
                float v = 0.f;
                if (row < M) {
                    if (k < DIMF) v = g_h[(size_t)row * DIMF + k];
                    else          v = sf[(size_t)sidx[row] * DIMF + (k - DIMF)];
                }
                As[lk + j][lr] = v;
            }
        }
        {
            #pragma unroll
            for (int j = 0; j < 8; j++) {
                int k = k0 + lk + j;
                Bs[lk + j][lr] = W[(size_t)lr * LDOUT + k];
            }
        }
        __syncthreads();
        #pragma unroll
        for (int kk = 0; kk < 16; kk++) {
            float4 a0 = *(const float4*)&As[kk][ty * 8];
            float4 a1 = *(const float4*)&As[kk][ty * 8 + 4];
            float4 b0 = *(const float4*)&Bs[kk][tx * 8];
            float4 b1 = *(const float4*)&Bs[kk][tx * 8 + 4];
            float ar[8] = {a0.x, a0.y, a0.z, a0.w, a1.x, a1.y, a1.z, a1.w};
            float br[8] = {b0.x, b0.y, b0.z, b0.w, b1.x, b1.y, b1.z, b1.w};
            #pragma unroll
            for (int i = 0; i < 8; i++)
                #pragma unroll
                for (int j = 0; j < 8; j++)
                    acc[i][j] += ar[i] * br[j];
        }
        __syncthreads();
    }

    // ---- relu(acc + bias) in regs; per-row partials into smem ----
    #pragma unroll
    for (int i = 0; i < 8; i++) {
        float s = 0.f, s2 = 0.f;
        #pragma unroll
        for (int j = 0; j < 8; j++) {
            int col = tx * 8 + j;
            float v = fmaxf(acc[i][j] + bias[col], 0.f);
            acc[i][j] = v;
            s += v;
            s2 = fmaf(v, v, s2);
        }
        redS [ty * 8 + i][tx] = s;
        redS2[ty * 8 + i][tx] = s2;
    }
    __syncthreads();

    // ---- per-row mean/rstd (threads 0..127, one row each) ----
    if (tid < 128) {
        float s = 0.f, s2 = 0.f;
        #pragma unroll
        for (int t = 0; t < 16; t++) { s += redS[tid][t]; s2 += redS2[tid][t]; }
        float mean = s * (1.f / DIMF);
        float var  = s2 * (1.f / DIMF) - mean * mean;
        rowMean[tid] = mean;
        rowRstd[tid] = rsqrtf(var + LN_EPS);
    }
    __syncthreads();

    // ---- normalize + affine + store to d_out ----
    #pragma unroll
    for (int i = 0; i < 8; i++) {
        int rloc = ty * 8 + i;
        int row = i0 + rloc;
        if (row >= M) continue;
        float mean = rowMean[rloc], rstd = rowRstd[rloc];
        #pragma unroll
        for (int j = 0; j < 8; j++) {
            int col = tx * 8 + j;
            outp[(size_t)row * DIMF + col] =
                (acc[i][j] - mean) * rstd * __ldg(&ln_g[col]) + __ldg(&ln_b[col]);
        }
    }
}

// ---------------- launcher ----------------
extern "C" void kernel_launch(void* const* d_in, const int* in_sizes, int n_in,
                              void* d_out, int out_size) {
    const float* src_feat = (const float*)d_in[0];
    const float* edge_f   = (const float*)d_in[1];
    const float* edge_dt  = (const float*)d_in[2];
    const float* time_w   = (const float*)d_in[3];
    const float* time_b   = (const float*)d_in[4];
    const float* wq_w     = (const float*)d_in[5];
    const float* wq_b     = (const float*)d_in[6];
    const float* wk_w     = (const float*)d_in[7];
    const float* wk_b     = (const float*)d_in[8];
    const float* wv_w     = (const float*)d_in[9];
    const float* wv_b     = (const float*)d_in[10];
    const float* wout_w   = (const float*)d_in[11];
    const float* wout_b   = (const float*)d_in[12];
    const float* ln_g     = (const float*)d_in[13];
    const float* ln_b     = (const float*)d_in[14];
    const int*   src_idx  = (const int*)d_in[15];   // JAX x64-disabled: int32
    const int*   edge_dst = (const int*)d_in[16];   // JAX x64-disabled: int32

    const int E = in_sizes[1] / DIMF;
    const int D = in_sizes[0] / DIMF - E;

    qb2_kernel<<<1, 128>>>(wq_w, wq_b, time_b);
    nstart_kernel<<<(D + 1 + 255) / 256, 256>>>(edge_dst, E, D);

    // Qd = gathered node feats @ wq[:, :128]^T + qb2
    gemm_q<<<(D + 127) / 128, 256>>>(wq_w, src_feat, src_idx, D);

    // tQ[d,h,:] = Wk_h^T Q_h[d]  (folds K projection into destinations)
    {
        dim3 grid((D + 31) / 32, 8);
        tq_kernel<<<grid, 256>>>(wk_w, wk_b, D);
    }

    // online-softmax attention; 2 warps per destination (one per 4-head group)
    {
        int warps = 2 * D;
        edge_kernel<<<(warps + 3) / 4, 128>>>(src_feat, src_idx, edge_f, edge_dt,
                                              time_w, time_b, D, E);
    }

    // h[d] = Wv_ext @ xbar[d]
    {
        int warps = 8 * ((D + 1) / 2);
        hproj_kernel<<<(warps * 32 + 255) / 256, 256>>>(wv_w, wv_b, D);
    }

    // output projection + ReLU + LayerNorm -> d_out
    gemm_out<<<(D + 127) / 128, 256>>>(wout_w, wout_b, src_feat, src_idx,
                                       ln_g, ln_b, (float*)d_out, D);
}